// round 17
// baseline (speedup 1.0000x reference)
#include <cuda_runtime.h>
#include <cstdint>
#include <math.h>

#define NN 4096
#define BB 2
#define TT 25
#define OFFCAP 4096
#define RR2 1089
#define EH 4032
#define HASHN 8192
#define HASHMASK 8191
#define EMPTY64 0xFFFFFFFFFFFFFFFFULL

typedef unsigned long long u64;
typedef unsigned short u16;

// ---- device scratch ----
__device__ float g_f[BB][NN];
__device__ float g_land[BB][50];
__device__ int g_arrive;    // monotonically increasing arrival counter (parity-based)

// ============================================================
// Compile-time offsets table: all (di,dj) with di^2+dj^2 <= 1089,
// sorted by (r^2, then lexicographic (di,dj)).
// ============================================================
struct OffTab {
    unsigned short p[OFFCAP];   // (di+33)<<7 | (dj+33); pad 0xFFFF
    float d2[OFFCAP];           // r^2 * (224/63)^2 ; pad 0
};

constexpr OffTab make_offtab() {
    OffTab t{};
    for (int i = 0; i < OFFCAP; ++i) { t.p[i] = 0xFFFF; t.d2[i] = 0.0f; }
    int hist[RR2 + 1] = {};
    for (int a = -33; a <= 33; ++a)
        for (int b = -33; b <= 33; ++b) {
            int r2 = a * a + b * b;
            if (r2 <= RR2) hist[r2]++;
        }
    int pos[RR2 + 1] = {};
    int run = 0;
    for (int r2 = 0; r2 <= RR2; ++r2) { pos[r2] = run; run += hist[r2]; }
    double s2 = (224.0 / 63.0) * (224.0 / 63.0);
    for (int a = -33; a <= 33; ++a)
        for (int b = -33; b <= 33; ++b) {
            int r2 = a * a + b * b;
            if (r2 > RR2) continue;
            int p = pos[r2]++;
            t.p[p] = (unsigned short)(((a + 33) << 7) | (b + 33));
            t.d2[p] = (float)((double)r2 * s2);
        }
    return t;
}

__constant__ OffTab g_tab = make_offtab();

// ============================================================
// Kernel 1: weighted DTM, early-terminating prefix walk.
// ============================================================
__global__ void k_dtm(const float* __restrict__ w_in) {
    __shared__ float sw[NN];
    __shared__ float s_ws[4];
    __shared__ float s_thr;
    int b = blockIdx.y;
    const float* w = w_in + b * NN;
    for (int i = threadIdx.x; i < NN; i += blockDim.x) sw[i] = w[i];
    __syncthreads();
    float ps = 0.f;
    for (int i = threadIdx.x; i < NN; i += blockDim.x) ps += sw[i];
    for (int o = 16; o; o >>= 1) ps += __shfl_xor_sync(~0u, ps, o);
    if ((threadIdx.x & 31) == 0) s_ws[threadIdx.x >> 5] = ps;
    __syncthreads();
    if (threadIdx.x == 0) s_thr = 0.05f * (((s_ws[0] + s_ws[1]) + s_ws[2]) + s_ws[3]);
    __syncthreads();
    float thr = s_thr;

    int p = blockIdx.x * blockDim.x + threadIdx.x;
    int i1 = (p >> 6) - 33, j1 = (p & 63) - 33;
    float excl = 0.f, acc = 0.f;
    for (int t = 0; t < OFFCAP; t += 8) {
        #pragma unroll
        for (int s = 0; s < 8; ++s) {
            unsigned op = (unsigned)g_tab.p[t + s];
            float d2 = g_tab.d2[t + s];
            int ni = i1 + (int)(op >> 7);
            int nj = j1 + (int)(op & 127u);
            float wv = 0.f;
            if (((ni | nj) & ~63) == 0) wv = sw[(ni << 6) | nj];
            float eff = fmaxf(fminf(thr - excl, wv), 0.f);
            acc = fmaf(eff, d2, acc);
            excl += wv;
        }
        if (excl >= thr) break;
    }
    g_f[b][p] = sqrtf(acc / thr);
}

// ============================================================
// Kernel 2: persistence — sortless watershed (direct root chase)
// + hash saddle dedup + tiny sorted Kruskal, landscape, MLP head.
//
// smem layout (bytes):
//   vkey  u64[4096]   0      .. 32768   (fbits<<12 | v, per-vertex)
//   tabl  u64[8192]   32768  .. 98304   (pair hash; later wbuf)
//   earr  u64[8192]   98304  .. 163840  (dedup'd saddle records)
//   ptrA  u16[4096]   163840 .. 172032
//   broot u16[4096]   180224 .. 188416  (basin root vertex)
//   par   u16[4096]   188416 .. 196608  (UF over vertex ids)
//   s_b   f32[2048]   196608 .. 204800
//   s_d   f32[2048]   204800 .. 212992
// ============================================================
__global__ void k_ph0(const float* __restrict__ Wg, const float* __restrict__ bg,
                      const float* __restrict__ Wfc, const float* __restrict__ bfc,
                      float* __restrict__ out) {
    extern __shared__ char sm[];
    u64* vkey  = (u64*)sm;
    u64* tabl  = (u64*)(sm + 32768);
    u64* earr  = (u64*)(sm + 98304);
    u16* ptrA  = (u16*)(sm + 163840);
    u16* broot = (u16*)(sm + 180224);
    u16* par   = (u16*)(sm + 188416);
    float* s_b = (float*)(sm + 196608);
    float* s_d = (float*)(sm + 204800);
    __shared__ int s_nb, s_cnt, s_m, s_last;
    __shared__ u64 s_minkey, s_maxkey;
    __shared__ float s_land[BB][50];
    __shared__ float s_x[BB][50];
    int b = blockIdx.x, tid = threadIdx.x;
    int warp = tid >> 5, lane = tid & 31;

    // A. per-vertex keys (f, index) lexicographic; hash init; counters
    for (int i = tid; i < NN; i += 1024) {
        unsigned fb = __float_as_uint(g_f[b][i]);   // f>=0 -> order-preserving bits
        vkey[i] = ((u64)fb << 12) | (unsigned)i;
    }
    for (int i = tid; i < HASHN; i += 1024) tabl[i] = EMPTY64;
    if (tid == 0) { s_nb = 0; s_m = 0; s_minkey = EMPTY64; s_maxkey = 0ULL; }
    __syncthreads();

    // B. global min/max key + steepest descent (argmin neighbor key)
    {
        u64 mn = EMPTY64, mx = 0ULL;
        for (int v = tid; v < NN; v += 1024) {
            u64 kv = vkey[v];
            mn = mn < kv ? mn : kv;
            mx = mx > kv ? mx : kv;
            int i = v >> 6, j = v & 63;
            u64 bk = kv; int bv = v;
            if (j > 0)  { u64 k = vkey[v - 1];  if (k < bk) { bk = k; bv = v - 1; } }
            if (j < 63) { u64 k = vkey[v + 1];  if (k < bk) { bk = k; bv = v + 1; } }
            if (i > 0)  { u64 k = vkey[v - 64]; if (k < bk) { bk = k; bv = v - 64; } }
            if (i < 63) { u64 k = vkey[v + 64]; if (k < bk) { bk = k; bv = v + 64; } }
            ptrA[v] = (u16)bv;
        }
        for (int o = 16; o; o >>= 1) {
            u64 t1 = __shfl_xor_sync(~0u, mn, o); mn = mn < t1 ? mn : t1;
            u64 t2 = __shfl_xor_sync(~0u, mx, o); mx = mx > t2 ? mx : t2;
        }
        if (lane == 0) {
            atomicMin((unsigned long long*)&s_minkey, mn);
            atomicMax((unsigned long long*)&s_maxkey, mx);
        }
    }
    __syncthreads();

    // C. direct root chase with path halving (ptrA is a fixed forest;
    //    halving writes are benign races — ancestors only, no tearing
    //    on aligned u16). Replaces 12 pointer-jumping rounds + barriers.
    {
        int nbloc = 0;
        for (int v = tid; v < NN; v += 1024) {
            int r = v;
            for (;;) {
                int p1 = ptrA[r];
                if (p1 == r) break;
                int gp = ptrA[p1];
                if (gp == p1) { r = p1; break; }
                ptrA[r] = (u16)gp; r = gp;
            }
            broot[v] = (u16)r;
            par[v] = (u16)v;
            if (r == v) nbloc++;
        }
        for (int o = 16; o; o >>= 1) nbloc += __shfl_xor_sync(~0u, nbloc, o);
        if ((tid & 31) == 0) atomicAdd(&s_nb, nbloc);
    }
    __syncthreads();

    // F. saddle dedup: per basin pair keep min-weight boundary edge.
    //    record = deathfbits<<24 | a<<12 | c  (a<c basin root vertices)
    for (int e = tid; e < 8064; e += 1024) {
        int u, v;
        if (e < EH) { int r = e / 63, c = e - r * 63; u = (r << 6) + c; v = u + 1; }
        else        { u = e - EH; v = u + 64; }
        int ru = broot[u], rv = broot[v];
        if (ru == rv) continue;
        u64 ku = vkey[u], kv = vkey[v];
        u64 wk = ku > kv ? ku : kv;
        unsigned fb = (unsigned)(wk >> 12);
        int a = ru < rv ? ru : rv;
        int c = ru < rv ? rv : ru;
        unsigned pk = ((unsigned)a << 12) | (unsigned)c;
        u64 rec = ((u64)fb << 24) | pk;
        unsigned slot = (pk * 2654435761u) >> 19;   // 13-bit hash
        for (;;) {
            u64 cur = tabl[slot];
            if (cur == EMPTY64) {
                u64 prev = atomicCAS((unsigned long long*)&tabl[slot], EMPTY64, rec);
                if (prev == EMPTY64) break;
                cur = prev;
            }
            if ((unsigned)(cur & 0xFFFFFFu) == pk) {
                atomicMin((unsigned long long*)&tabl[slot], rec);
                break;
            }
            slot = (slot + 1) & HASHMASK;
        }
    }
    __syncthreads();

    // G. compact table entries into earr
    for (int i = tid; i < HASHN; i += 1024) {
        u64 r = tabl[i];
        if (r != EMPTY64) earr[atomicAdd(&s_m, 1)] = r;
    }
    __syncthreads();
    int m = s_m;
    int P = 32; while (P < m) P <<= 1;
    for (int i = m + tid; i < P; i += 1024) earr[i] = EMPTY64;
    __syncthreads();

    // H. bitonic sort earr[0..P) (unique keys -> deterministic)
    for (int k = 2; k <= P; k <<= 1)
        for (int j = k >> 1; j > 0; j >>= 1) {
            for (int p = tid; p < (P >> 1); p += 1024) {
                int i = ((p & ~(j - 1)) << 1) | (p & (j - 1));
                int ix = i | j;
                u64 a = earr[i], c = earr[ix];
                if ((a > c) == ((i & k) == 0)) { earr[i] = c; earr[ix] = a; }
            }
            __syncthreads();
        }

    // I. warp 0: speculative warp-parallel Kruskal over saddles.
    //    Other warps: preload MLP weights into tabl (free now).
    if (warp == 0) {
        int nb = s_nb, cnt = 0;
        for (int base = 0; base < m && cnt < nb - 1; base += 32) {
            int idx = base + lane;
            bool ok = idx < m;
            u64 rec = ok ? earr[idx] : 0;
            int ra = -1, rb = -1;
            if (ok) {
                ra = (int)((rec >> 12) & 4095ULL);
                rb = (int)(rec & 4095ULL);
                for (;;) {
                    int p1 = par[ra];
                    if (p1 == ra) break;
                    int gp = par[p1];
                    if (gp == p1) { ra = p1; break; }
                    par[ra] = (u16)gp; ra = gp;
                }
                for (;;) {
                    int p1 = par[rb];
                    if (p1 == rb) break;
                    int gp = par[p1];
                    if (gp == p1) { rb = p1; break; }
                    par[rb] = (u16)gp; rb = gp;
                }
            }
            __syncwarp();
            unsigned todo = __ballot_sync(0xffffffffu, ok && (ra != rb));
            while (todo) {
                int l = __ffs(todo) - 1; todo &= todo - 1;
                // ALL lanes participate in every shuffle (convergent code)
                int ra_l = __shfl_sync(0xffffffffu, ra, l);
                int rb_l = __shfl_sync(0xffffffffu, rb, l);
                u64 rec_l = __shfl_sync(0xffffffffu, rec, l);
                if (ra_l != rb_l) {
                    // elder = smaller (f, vid) key — matches reference exactly
                    bool ue = vkey[ra_l] < vkey[rb_l];
                    int eld = ue ? ra_l : rb_l;
                    int yng = ue ? rb_l : ra_l;
                    if (lane == l) {
                        par[yng] = (u16)eld;
                        s_b[cnt] = __uint_as_float((unsigned)(vkey[yng] >> 12));
                        s_d[cnt] = __uint_as_float((unsigned)(rec_l >> 24));
                    }
                    cnt++;
                    if (ra == yng) ra = eld;   // in-register staleness repair
                    if (rb == yng) rb = eld;
                }
            }
            __syncwarp();
        }
        if (lane == 0) {   // appended global bar (f.min, f.max)
            s_b[cnt] = __uint_as_float((unsigned)(s_minkey >> 12));
            s_d[cnt] = __uint_as_float((unsigned)(s_maxkey >> 12));
            s_cnt = cnt;
        }
    } else {
        // overlap: weights into wbuf = tabl region
        float* wbuf = (float*)tabl;
        for (int i = tid - 32; i < 2500; i += 992) wbuf[i] = Wg[i];
        for (int i = tid - 32; i < 500; i += 992) wbuf[2500 + i] = Wfc[i];
    }
    __syncthreads();

    // J. landscape: warp w -> t index w; only cnt+1 bars
    int cnt = s_cnt;
    if (warp < TT) {
        float tv = 1.875f * (float)warp;    // linspace(0,45,25) exact
        float m1 = 0.f, m2 = 0.f;           // zero bars contribute 0
        for (int i = lane; i <= cnt; i += 32) {
            float bi = s_b[i], di = s_d[i];
            float tri = fminf(tv - bi, di - tv);
            tri = fmaxf(tri, 0.f);
            if (tri > m1)      { m2 = m1; m1 = tri; }
            else if (tri > m2) { m2 = tri; }
        }
        for (int o = 16; o; o >>= 1) {
            float o1 = __shfl_xor_sync(~0u, m1, o);
            float o2 = __shfl_xor_sync(~0u, m2, o);
            float n1 = fmaxf(m1, o1);
            float n2 = fmaxf(fminf(m1, o1), fmaxf(m2, o2));
            m1 = n1; m2 = n2;
        }
        if (lane == 0) { g_land[b][warp] = m1; g_land[b][TT + warp] = m2; }
    }
    __syncthreads();

    // K. last block runs the MLP head (parity arrival counter:
    // each launch adds exactly BB=2 arrivals; odd old-value marks
    // the last block of this launch on every graph replay).
    __threadfence();
    if (tid == 0) s_last = ((atomicAdd(&g_arrive, 1) & 1) == 1) ? 1 : 0;
    __syncthreads();
    if (s_last) {
        float* wbuf = (float*)tabl;   // preloaded during phase I
        if (tid < BB * 50) {
            int bb = tid / 50, o = tid - bb * 50;
            s_land[bb][o] = g_land[bb][o];
        }
        __syncthreads();
        if (tid < BB * 50) {
            int bb = tid / 50, o = tid - bb * 50;
            float s = bg[o];
            #pragma unroll 10
            for (int i = 0; i < 50; ++i) s += s_land[bb][i] * wbuf[o * 50 + i];
            s_x[bb][o] = s;
        }
        __syncthreads();
        if (tid < 50) out[20 + tid] = fabsf(s_x[0][tid]) + fabsf(s_x[1][tid]);
        if (tid < BB * 10) {
            int bb = tid / 10, j = tid - bb * 10;
            float s = bfc[j];
            #pragma unroll 10
            for (int o = 0; o < 50; ++o) s += fmaxf(s_x[bb][o], 0.f) * wbuf[2500 + j * 50 + o];
            out[bb * 10 + j] = s;
        }
    }
}

// ============================================================
extern "C" void kernel_launch(void* const* d_in, const int* in_sizes, int n_in,
                              void* d_out, int out_size) {
    const float* input = (const float*)d_in[0];   // [2,1,64,64]
    const float* Wg    = (const float*)d_in[1];   // [50,50]
    const float* bg    = (const float*)d_in[2];   // [50]
    const float* Wfc   = (const float*)d_in[3];   // [10,50]
    const float* bfc   = (const float*)d_in[4];   // [10]
    float* out = (float*)d_out;

    cudaFuncSetAttribute(k_ph0, cudaFuncAttributeMaxDynamicSharedMemorySize, 212992);

    dim3 g(NN / 128, BB);
    k_dtm<<<g, 128>>>(input);
    k_ph0<<<BB, 1024, 212992>>>(Wg, bg, Wfc, bfc, out);
}